// round 12
// baseline (speedup 1.0000x reference)
#include <cuda_runtime.h>
#include <math.h>

#define H 256
#define DIN 700
#define DOUT 20
#define BATCH 128
#define TT 250

// Scratch (device globals). g_X1 is T-MAJOR: X1[t][b][i].
// Weight tables have an extra all-zero row (index 256) for padded gathers.
__device__ float g_X1[(size_t)TT * BATCH * H];
__device__ float g_W11T[(H + 1) * H];
__device__ float g_W12T[(H + 1) * H];
__device__ float g_W22T[(H + 1) * H];

// ---------------------------------------------------------------------------
__device__ __forceinline__ void ffma2(unsigned long long& acc,
                                      unsigned long long a,
                                      unsigned long long b) {
    asm("fma.rn.f32x2 %0, %1, %2, %0;" : "+l"(acc) : "l"(a), "l"(b));
}
__device__ __forceinline__ unsigned long long pack2(float lo, float hi) {
    unsigned long long r;
    asm("mov.b64 %0, {%1, %2};" : "=l"(r) : "f"(lo), "f"(hi));
    return r;
}
__device__ __forceinline__ void unpack2(unsigned long long v, float& lo, float& hi) {
    asm("mov.b64 {%0, %1}, %2;" : "=f"(lo), "=f"(hi) : "l"(v));
}
// Named barrier over 512 threads (one sample pipeline). ids 1 and 2.
__device__ __forceinline__ void bar_half(int id) {
    asm volatile("bar.sync %0, %1;" :: "r"(id), "r"(512) : "memory");
}

// ---------------------------------------------------------------------------
__global__ void transpose_weights_kernel(const float* __restrict__ W11,
                                         const float* __restrict__ W12,
                                         const float* __restrict__ W22) {
    int idx = blockIdx.x * blockDim.x + threadIdx.x;
    if (idx < 3 * H * H) {
        int m = idx >> 16;
        int r = (idx >> 8) & 255;
        int c = idx & 255;
        if (m == 0)      g_W11T[c * H + r] = W11[r * H + c];
        else if (m == 1) g_W12T[c * H + r] = W12[r * H + c];
        else             g_W22T[c * H + r] = W22[r * H + c];
    } else {
        int w = idx - 3 * H * H;
        if (w < 3 * H) {
            int m = w >> 8, c = w & 255;
            if (m == 0)      g_W11T[256 * H + c] = 0.f;
            else if (m == 1) g_W12T[256 * H + c] = 0.f;
            else             g_W22T[256 * H + c] = 0.f;
        }
    }
}

// ---------------------------------------------------------------------------
// X1[t][b][:] = x[b][t][:] @ Wi1.T + (bi1 + b11). Block y == timestep.
// (R10's proven serial GEMM, unchanged.)
// ---------------------------------------------------------------------------
#define GBM 128
#define GBN 128
#define GBK 16
#define GPAD 4
#define GNT ((DIN + GBK - 1) / GBK)

__global__ __launch_bounds__(256, 2) void gemm_x1_kernel(
    const float* __restrict__ x, const float* __restrict__ Wi1,
    const float* __restrict__ bi1, const float* __restrict__ b11) {
    __shared__ float As[2][GBK][GBM + GPAD];
    __shared__ float Bs[2][GBK][GBN + GPAD];

    int tid = threadIdx.x;
    int tstep = blockIdx.y;
    int n0 = blockIdx.x * GBN;
    int tx = tid & 15, ty = tid >> 4;

    int row0 = tid >> 2,          kc0 = tid & 3;
    int row1 = (256 + tid) >> 2,  kc1 = tid & 3;

    const float* xr0 = x + ((size_t)row0 * TT + tstep) * DIN;
    const float* xr1 = x + ((size_t)row1 * TT + tstep) * DIN;

    unsigned long long acc[4][8];
#pragma unroll
    for (int r = 0; r < 4; ++r)
#pragma unroll
        for (int c = 0; c < 8; ++c) acc[r][c] = 0ull;

    float4 stA0, stA1, stB0, stB1;

    {
        int kA0 = kc0 * 4, kA1 = kc1 * 4;
        stA0 = *(const float4*)(xr0 + kA0);
        stA1 = *(const float4*)(xr1 + kA1);
        stB0 = *(const float4*)(Wi1 + (size_t)(n0 + row0) * DIN + kA0);
        stB1 = *(const float4*)(Wi1 + (size_t)(n0 + row1) * DIN + kA1);
        As[0][kc0 * 4 + 0][row0] = stA0.x; As[0][kc0 * 4 + 1][row0] = stA0.y;
        As[0][kc0 * 4 + 2][row0] = stA0.z; As[0][kc0 * 4 + 3][row0] = stA0.w;
        As[0][kc1 * 4 + 0][row1] = stA1.x; As[0][kc1 * 4 + 1][row1] = stA1.y;
        As[0][kc1 * 4 + 2][row1] = stA1.z; As[0][kc1 * 4 + 3][row1] = stA1.w;
        Bs[0][kc0 * 4 + 0][row0] = stB0.x; Bs[0][kc0 * 4 + 1][row0] = stB0.y;
        Bs[0][kc0 * 4 + 2][row0] = stB0.z; Bs[0][kc0 * 4 + 3][row0] = stB0.w;
        Bs[0][kc1 * 4 + 0][row1] = stB1.x; Bs[0][kc1 * 4 + 1][row1] = stB1.y;
        Bs[0][kc1 * 4 + 2][row1] = stB1.z; Bs[0][kc1 * 4 + 3][row1] = stB1.w;
    }
    __syncthreads();

    for (int t = 0; t < GNT; ++t) {
        int buf = t & 1;

        if (t + 1 < GNT) {
            int kb = (t + 1) * GBK;
            int kA0 = kb + kc0 * 4, kA1 = kb + kc1 * 4;
            stA0 = (kA0 < DIN) ? *(const float4*)(xr0 + kA0) : make_float4(0.f,0.f,0.f,0.f);
            stA1 = (kA1 < DIN) ? *(const float4*)(xr1 + kA1) : make_float4(0.f,0.f,0.f,0.f);
            stB0 = (kA0 < DIN) ? *(const float4*)(Wi1 + (size_t)(n0 + row0) * DIN + kA0)
                               : make_float4(0.f, 0.f, 0.f, 0.f);
            stB1 = (kA1 < DIN) ? *(const float4*)(Wi1 + (size_t)(n0 + row1) * DIN + kA1)
                               : make_float4(0.f, 0.f, 0.f, 0.f);
        }

#pragma unroll
        for (int kk = 0; kk < GBK; ++kk) {
            ulonglong2 aA = *(const ulonglong2*)&As[buf][kk][ty * 8];
            ulonglong2 aB = *(const ulonglong2*)&As[buf][kk][ty * 8 + 4];
            float4 b0 = *(const float4*)&Bs[buf][kk][tx * 8];
            float4 b1 = *(const float4*)&Bs[buf][kk][tx * 8 + 4];
            float barr[8] = {b0.x, b0.y, b0.z, b0.w, b1.x, b1.y, b1.z, b1.w};
#pragma unroll
            for (int c = 0; c < 8; ++c) {
                unsigned long long bb = pack2(barr[c], barr[c]);
                ffma2(acc[0][c], aA.x, bb);
                ffma2(acc[1][c], aA.y, bb);
                ffma2(acc[2][c], aB.x, bb);
                ffma2(acc[3][c], aB.y, bb);
            }
        }

        if (t + 1 < GNT) {
            int nb = buf ^ 1;
            As[nb][kc0 * 4 + 0][row0] = stA0.x; As[nb][kc0 * 4 + 1][row0] = stA0.y;
            As[nb][kc0 * 4 + 2][row0] = stA0.z; As[nb][kc0 * 4 + 3][row0] = stA0.w;
            As[nb][kc1 * 4 + 0][row1] = stA1.x; As[nb][kc1 * 4 + 1][row1] = stA1.y;
            As[nb][kc1 * 4 + 2][row1] = stA1.z; As[nb][kc1 * 4 + 3][row1] = stA1.w;
            Bs[nb][kc0 * 4 + 0][row0] = stB0.x; Bs[nb][kc0 * 4 + 1][row0] = stB0.y;
            Bs[nb][kc0 * 4 + 2][row0] = stB0.z; Bs[nb][kc0 * 4 + 3][row0] = stB0.w;
            Bs[nb][kc1 * 4 + 0][row1] = stB1.x; Bs[nb][kc1 * 4 + 1][row1] = stB1.y;
            Bs[nb][kc1 * 4 + 2][row1] = stB1.z; Bs[nb][kc1 * 4 + 3][row1] = stB1.w;
        }
        __syncthreads();
    }

    float bias[8];
#pragma unroll
    for (int c = 0; c < 8; ++c) {
        int n = n0 + tx * 8 + c;
        bias[c] = bi1[n] + b11[n];
    }
    float* X1t = g_X1 + (size_t)tstep * BATCH * H;
#pragma unroll
    for (int r2 = 0; r2 < 4; ++r2) {
        float lo[8], hi[8];
#pragma unroll
        for (int c = 0; c < 8; ++c) unpack2(acc[r2][c], lo[c], hi[c]);
        int bA = ty * 8 + 2 * r2;
        int bB = bA + 1;
        int n = n0 + tx * 8;
        float4* pA = (float4*)(X1t + (size_t)bA * H + n);
        float4* pB = (float4*)(X1t + (size_t)bB * H + n);
        pA[0] = make_float4(lo[0] + bias[0], lo[1] + bias[1], lo[2] + bias[2], lo[3] + bias[3]);
        pA[1] = make_float4(lo[4] + bias[4], lo[5] + bias[5], lo[6] + bias[6], lo[7] + bias[7]);
        pB[0] = make_float4(hi[0] + bias[0], hi[1] + bias[1], hi[2] + bias[2], hi[3] + bias[3]);
        pB[1] = make_float4(hi[4] + bias[4], hi[5] + bias[5], hi[6] + bias[6], hi[7] + bias[7]);
    }
}

// ---------------------------------------------------------------------------
__device__ __forceinline__ void acc4(const float* __restrict__ W,
                                     int4 j, int col, float4& h) {
    float4 v0 = *(const float4*)(W + j.x * H + col);
    float4 v1 = *(const float4*)(W + j.y * H + col);
    float4 v2 = *(const float4*)(W + j.z * H + col);
    float4 v3 = *(const float4*)(W + j.w * H + col);
    h.x += (v0.x + v1.x) + (v2.x + v3.x);
    h.y += (v0.y + v1.y) + (v2.y + v3.y);
    h.z += (v0.z + v1.z) + (v2.z + v3.z);
    h.w += (v0.w + v1.w) + (v2.w + v3.w);
}

// ---------------------------------------------------------------------------
// Persistent RNN: TWO samples per CTA, 1024 threads. Threads [0,512) run
// sample 2b, [512,1024) run sample 2b+1 as independent pipelines with
// private named barriers (bar.sync 1/2, 512 threads each). While one
// pipeline waits at a barrier or on L2 gathers, the other's 16 warps issue.
// Per-pipeline structure identical to R10 (segmented lists, rotated chunks).
// ---------------------------------------------------------------------------
__global__ __launch_bounds__(1024, 1) void rnn_kernel(
    const float* __restrict__ mem1_0, const float* __restrict__ mem2_0,
    const float* __restrict__ memo_0,
    const float* __restrict__ b12v, const float* __restrict__ b22v,
    const float* __restrict__ Wo, const float* __restrict__ bov,
    const float* __restrict__ tau_adp1, const float* __restrict__ tau_adp2,
    const float* __restrict__ tau_m1, const float* __restrict__ tau_m2,
    const float* __restrict__ tau_mo,
    float* __restrict__ out) {
    __shared__ __align__(16) int list1[2][2][H];     // [half][phase][slot]
    __shared__ __align__(16) int list2[2][2][H];
    __shared__ int cntp1[2][2][8], cntp2[2][2][8];   // [half][phase][seg]
    __shared__ float part11[2][8][H];
    __shared__ float part22[2][8][H];
    __shared__ float part12[2][8][H];
    __shared__ float pout[2][8][32];
    __shared__ float sWoT[(H + 1) * DOUT];           // shared by both halves

    int tid = threadIdx.x;
    int half = tid >> 9;               // 0 or 1
    int t5 = tid & 511;                // tid within pipeline
    int lane = t5 & 31, warp = t5 >> 5;
    int rep = t5 >> 6;
    int col = (t5 & 63) << 2;
    int barid = half + 1;
    int b = blockIdx.x * 2 + half;     // sample

    for (int idx = tid; idx < H * DOUT; idx += 1024) {
        int j = idx / DOUT, k = idx - j * DOUT;
        sWoT[idx] = Wo[k * H + j];
    }
    if (tid < DOUT) sWoT[H * DOUT + tid] = 0.f;
    if (t5 < 8) {
        cntp1[half][0][t5] = 0; cntp1[half][1][t5] = 0;
        cntp2[half][0][t5] = 0; cntp2[half][1][t5] = 0;
    }

    float mem1 = 0.f, sp1 = 0.f, ab1 = 0.01f, al1 = 0.f, ro1 = 0.f;
    float mem2 = 0.f, sp2 = 0.f, ab2 = 0.01f, al2 = 0.f, ro2 = 0.f;
    float hb2 = 0.f;
    float memo = 0.f, alo = 0.f, omo = 0.f, bok = 0.f, accv = 0.f;
    if (t5 < 256) {
        mem1 = mem1_0[b * H + t5];
        al1 = expf(-1.f / tau_m1[t5]);
        ro1 = expf(-1.f / tau_adp1[t5]);
        mem2 = mem2_0[b * H + t5];
        al2 = expf(-1.f / tau_m2[t5]);
        ro2 = expf(-1.f / tau_adp2[t5]);
        hb2 = b12v[t5] + b22v[t5];
        if (t5 < DOUT) {
            memo = memo_0[b * DOUT + t5];
            alo = expf(-1.f / tau_mo[t5]); omo = 1.f - alo;
            bok = bov[t5];
        }
    }
    __syncthreads();   // whole-CTA: sWoT + counters visible to both halves

    int p = 0;
    float x1cur = (t5 < 256) ? g_X1[(size_t)b * H + t5] : 0.f;

    for (int t = 0; t < TT; ++t) {
        int pn = p ^ 1;

        float x1nxt = 0.f;
        if (t5 < 256 && t + 1 < TT)
            x1nxt = g_X1[((size_t)(t + 1) * BATCH + b) * H + t5];

        // ---- phase A: fused W11 (old sp1) + W22 (old sp2) segmented gather ----
        {
            float4 a11 = make_float4(0.f, 0.f, 0.f, 0.f);
            float4 a22 = make_float4(0.f, 0.f, 0.f, 0.f);
#pragma unroll
            for (int seg = 0; seg < 8; ++seg) {
                int ch = (rep + seg) & 7;        // rotated chunk assignment
                int c4 = ch << 2;
                int c1 = cntp1[half][p][seg];
                int c2 = cntp2[half][p][seg];
                const int4* s1 = (const int4*)&list1[half][p][seg << 5];
                const int4* s2 = (const int4*)&list2[half][p][seg << 5];
                if (c4 < c1) acc4(g_W11T, s1[ch], col, a11);
                if (c4 < c2) acc4(g_W22T, s2[ch], col, a22);
            }
            *(float4*)&part11[half][rep][col] = a11;
            *(float4*)&part22[half][rep][col] = a22;
        }
        bar_half(barid);   // (a)

        // ---- layer 1 update + segmented list write (owners) ----
        if (t5 < 256) {
            float h1 = x1cur;
#pragma unroll
            for (int r = 0; r < 8; ++r) h1 += part11[half][r][t5];
            ab1 = ro1 * ab1 + (1.f - ro1) * sp1;
            float B = 0.01f + 1.8f * ab1;
            mem1 = mem1 * al1 + (1.f - al1) * h1 - B * sp1;
            float sp1n = (mem1 - B) > 0.f ? 1.f : 0.f;
            unsigned bal = __ballot_sync(0xffffffffu, sp1n != 0.f);
            int cw = __popc(bal);
            int cwp = (cw + 3) & ~3;
            unsigned ltm = (1u << lane) - 1u;
            if (sp1n != 0.f) {
                list1[half][pn][(warp << 5) + __popc(bal & ltm)] = t5;
            } else {
                int np = __popc(~bal & ltm);
                if (np < cwp - cw) list1[half][pn][(warp << 5) + cw + np] = 256;
            }
            if (lane == 0) cntp1[half][pn][warp] = cwp;
            sp1 = sp1n;
        }
        bar_half(barid);   // (b)

        // ---- phase B: W12 segmented gather (new sp1) ----
        {
            float4 a12 = make_float4(0.f, 0.f, 0.f, 0.f);
#pragma unroll
            for (int seg = 0; seg < 8; ++seg) {
                int ch = (rep + seg) & 7;        // rotated chunk assignment
                int c1 = cntp1[half][pn][seg];
                const int4* s1 = (const int4*)&list1[half][pn][seg << 5];
                if ((ch << 2) < c1) acc4(g_W12T, s1[ch], col, a12);
            }
            *(float4*)&part12[half][rep][col] = a12;
        }
        bar_half(barid);   // (c)

        // ---- layer 2 update + list write + own-segment pout (owners) ----
        if (t5 < 256) {
            float h2 = hb2;
#pragma unroll
            for (int r = 0; r < 8; ++r) h2 += part12[half][r][t5];
#pragma unroll
            for (int r = 0; r < 8; ++r) h2 += part22[half][r][t5];
            ab2 = ro2 * ab2 + (1.f - ro2) * sp2;
            float B = 0.01f + 1.8f * ab2;
            mem2 = mem2 * al2 + (1.f - al2) * h2 - B * sp2;
            float sp2n = (mem2 - B) > 0.f ? 1.f : 0.f;
            unsigned bal = __ballot_sync(0xffffffffu, sp2n != 0.f);
            int cw = __popc(bal);
            int cwp = (cw + 3) & ~3;
            unsigned ltm = (1u << lane) - 1u;
            if (sp2n != 0.f) {
                list2[half][pn][(warp << 5) + __popc(bal & ltm)] = t5;
            } else {
                int np = __popc(~bal & ltm);
                if (np < cwp - cw) list2[half][pn][(warp << 5) + cw + np] = 256;
            }
            if (lane == 0) cntp2[half][pn][warp] = cwp;
            sp2 = sp2n;

            // output partial for this warp's 32 neurons (ballot in register)
            int kk = lane < DOUT ? lane : 0;
            float o = 0.f;
            unsigned mm = bal;
            int jb = warp << 5;
            while (mm) {
                int l = __ffs(mm) - 1;
                mm &= mm - 1;
                o += sWoT[(jb + l) * DOUT + kk];
            }
            pout[half][warp][lane] = o;
        }
        bar_half(barid);   // (d)

        // ---- output: warp 0 of the half sums partials + softmax ----
        if (warp == 0) {
            float o = bok;
#pragma unroll
            for (int g = 0; g < 8; ++g) o += pout[half][g][lane];
            memo = memo * alo + omo * o;
            float e = lane < DOUT ? __expf(memo) : 0.f;
            float ss = e;
#pragma unroll
            for (int sh = 16; sh > 0; sh >>= 1)
                ss += __shfl_xor_sync(0xffffffffu, ss, sh);
            if (t > 10) accv += e / ss;
        }

        p = pn;
        x1cur = x1nxt;
    }

    if (t5 < DOUT) out[b * DOUT + t5] = accv;
}

// ---------------------------------------------------------------------------
// Serial single-stream launch (overlap permanently abandoned: R6/R8/R11).
// ---------------------------------------------------------------------------
extern "C" void kernel_launch(void* const* d_in, const int* in_sizes, int n_in,
                              void* d_out, int out_size) {
    const float* x        = (const float*)d_in[0];
    const float* mem1_0   = (const float*)d_in[1];
    const float* mem2_0   = (const float*)d_in[2];
    const float* memo_0   = (const float*)d_in[3];
    const float* Wi1      = (const float*)d_in[4];
    const float* bi1      = (const float*)d_in[5];
    const float* W11      = (const float*)d_in[6];
    const float* b11      = (const float*)d_in[7];
    const float* W12      = (const float*)d_in[8];
    const float* b12      = (const float*)d_in[9];
    const float* W22      = (const float*)d_in[10];
    const float* b22      = (const float*)d_in[11];
    const float* Wo       = (const float*)d_in[12];
    const float* bo       = (const float*)d_in[13];
    const float* tau_adp1 = (const float*)d_in[14];
    const float* tau_adp2 = (const float*)d_in[15];
    const float* tau_m1   = (const float*)d_in[16];
    const float* tau_m2   = (const float*)d_in[17];
    const float* tau_mo   = (const float*)d_in[18];
    float* out = (float*)d_out;

    transpose_weights_kernel<<<(3 * H * H + 3 * H + 255) / 256, 256>>>(W11, W12, W22);
    dim3 g(H / GBN, TT);   // (2, 250): block y == timestep
    gemm_x1_kernel<<<g, 256>>>(x, Wi1, bi1, b11);
    rnn_kernel<<<BATCH / 2, 1024>>>(mem1_0, mem2_0, memo_0, b12, b22, Wo, bo,
                                    tau_adp1, tau_adp2, tau_m1, tau_m2, tau_mo, out);
}

// round 13
// speedup vs baseline: 1.2460x; 1.2460x over previous
#include <cuda_runtime.h>
#include <math.h>

#define H 256
#define DIN 700
#define DOUT 20
#define BATCH 128
#define TT 250

// Scratch (device globals). g_X1 is T-MAJOR: X1[t][b][i].
// Weight tables have an extra all-zero row (index 256) for padded gathers.
__device__ float g_X1[(size_t)TT * BATCH * H];
__device__ float g_W11T[(H + 1) * H];
__device__ float g_W12T[(H + 1) * H];
__device__ float g_W22T[(H + 1) * H];

// ---------------------------------------------------------------------------
__device__ __forceinline__ void ffma2(unsigned long long& acc,
                                      unsigned long long a,
                                      unsigned long long b) {
    asm("fma.rn.f32x2 %0, %1, %2, %0;" : "+l"(acc) : "l"(a), "l"(b));
}
__device__ __forceinline__ unsigned long long pack2(float lo, float hi) {
    unsigned long long r;
    asm("mov.b64 %0, {%1, %2};" : "=l"(r) : "f"(lo), "f"(hi));
    return r;
}
__device__ __forceinline__ void unpack2(unsigned long long v, float& lo, float& hi) {
    asm("mov.b64 {%0, %1}, %2;" : "=f"(lo), "=f"(hi) : "l"(v));
}
// Named barrier over the 512 worker threads (warps 0-15).
__device__ __forceinline__ void bar_workers() {
    asm volatile("bar.sync 1, 512;" ::: "memory");
}

// ---------------------------------------------------------------------------
__global__ void transpose_weights_kernel(const float* __restrict__ W11,
                                         const float* __restrict__ W12,
                                         const float* __restrict__ W22) {
    int idx = blockIdx.x * blockDim.x + threadIdx.x;
    if (idx < 3 * H * H) {
        int m = idx >> 16;
        int r = (idx >> 8) & 255;
        int c = idx & 255;
        if (m == 0)      g_W11T[c * H + r] = W11[r * H + c];
        else if (m == 1) g_W12T[c * H + r] = W12[r * H + c];
        else             g_W22T[c * H + r] = W22[r * H + c];
    } else {
        int w = idx - 3 * H * H;
        if (w < 3 * H) {
            int m = w >> 8, c = w & 255;
            if (m == 0)      g_W11T[256 * H + c] = 0.f;
            else if (m == 1) g_W12T[256 * H + c] = 0.f;
            else             g_W22T[256 * H + c] = 0.f;
        }
    }
}

// ---------------------------------------------------------------------------
// X1[t][b][:] = x[b][t][:] @ Wi1.T + (bi1 + b11). Block y == timestep.
// (R10's proven serial GEMM, unchanged.)
// ---------------------------------------------------------------------------
#define GBM 128
#define GBN 128
#define GBK 16
#define GPAD 4
#define GNT ((DIN + GBK - 1) / GBK)

__global__ __launch_bounds__(256, 2) void gemm_x1_kernel(
    const float* __restrict__ x, const float* __restrict__ Wi1,
    const float* __restrict__ bi1, const float* __restrict__ b11) {
    __shared__ float As[2][GBK][GBM + GPAD];
    __shared__ float Bs[2][GBK][GBN + GPAD];

    int tid = threadIdx.x;
    int tstep = blockIdx.y;
    int n0 = blockIdx.x * GBN;
    int tx = tid & 15, ty = tid >> 4;

    int row0 = tid >> 2,          kc0 = tid & 3;
    int row1 = (256 + tid) >> 2,  kc1 = tid & 3;

    const float* xr0 = x + ((size_t)row0 * TT + tstep) * DIN;
    const float* xr1 = x + ((size_t)row1 * TT + tstep) * DIN;

    unsigned long long acc[4][8];
#pragma unroll
    for (int r = 0; r < 4; ++r)
#pragma unroll
        for (int c = 0; c < 8; ++c) acc[r][c] = 0ull;

    float4 stA0, stA1, stB0, stB1;

    {
        int kA0 = kc0 * 4, kA1 = kc1 * 4;
        stA0 = *(const float4*)(xr0 + kA0);
        stA1 = *(const float4*)(xr1 + kA1);
        stB0 = *(const float4*)(Wi1 + (size_t)(n0 + row0) * DIN + kA0);
        stB1 = *(const float4*)(Wi1 + (size_t)(n0 + row1) * DIN + kA1);
        As[0][kc0 * 4 + 0][row0] = stA0.x; As[0][kc0 * 4 + 1][row0] = stA0.y;
        As[0][kc0 * 4 + 2][row0] = stA0.z; As[0][kc0 * 4 + 3][row0] = stA0.w;
        As[0][kc1 * 4 + 0][row1] = stA1.x; As[0][kc1 * 4 + 1][row1] = stA1.y;
        As[0][kc1 * 4 + 2][row1] = stA1.z; As[0][kc1 * 4 + 3][row1] = stA1.w;
        Bs[0][kc0 * 4 + 0][row0] = stB0.x; Bs[0][kc0 * 4 + 1][row0] = stB0.y;
        Bs[0][kc0 * 4 + 2][row0] = stB0.z; Bs[0][kc0 * 4 + 3][row0] = stB0.w;
        Bs[0][kc1 * 4 + 0][row1] = stB1.x; Bs[0][kc1 * 4 + 1][row1] = stB1.y;
        Bs[0][kc1 * 4 + 2][row1] = stB1.z; Bs[0][kc1 * 4 + 3][row1] = stB1.w;
    }
    __syncthreads();

    for (int t = 0; t < GNT; ++t) {
        int buf = t & 1;

        if (t + 1 < GNT) {
            int kb = (t + 1) * GBK;
            int kA0 = kb + kc0 * 4, kA1 = kb + kc1 * 4;
            stA0 = (kA0 < DIN) ? *(const float4*)(xr0 + kA0) : make_float4(0.f,0.f,0.f,0.f);
            stA1 = (kA1 < DIN) ? *(const float4*)(xr1 + kA1) : make_float4(0.f,0.f,0.f,0.f);
            stB0 = (kA0 < DIN) ? *(const float4*)(Wi1 + (size_t)(n0 + row0) * DIN + kA0)
                               : make_float4(0.f, 0.f, 0.f, 0.f);
            stB1 = (kA1 < DIN) ? *(const float4*)(Wi1 + (size_t)(n0 + row1) * DIN + kA1)
                               : make_float4(0.f, 0.f, 0.f, 0.f);
        }

#pragma unroll
        for (int kk = 0; kk < GBK; ++kk) {
            ulonglong2 aA = *(const ulonglong2*)&As[buf][kk][ty * 8];
            ulonglong2 aB = *(const ulonglong2*)&As[buf][kk][ty * 8 + 4];
            float4 b0 = *(const float4*)&Bs[buf][kk][tx * 8];
            float4 b1 = *(const float4*)&Bs[buf][kk][tx * 8 + 4];
            float barr[8] = {b0.x, b0.y, b0.z, b0.w, b1.x, b1.y, b1.z, b1.w};
#pragma unroll
            for (int c = 0; c < 8; ++c) {
                unsigned long long bb = pack2(barr[c], barr[c]);
                ffma2(acc[0][c], aA.x, bb);
                ffma2(acc[1][c], aA.y, bb);
                ffma2(acc[2][c], aB.x, bb);
                ffma2(acc[3][c], aB.y, bb);
            }
        }

        if (t + 1 < GNT) {
            int nb = buf ^ 1;
            As[nb][kc0 * 4 + 0][row0] = stA0.x; As[nb][kc0 * 4 + 1][row0] = stA0.y;
            As[nb][kc0 * 4 + 2][row0] = stA0.z; As[nb][kc0 * 4 + 3][row0] = stA0.w;
            As[nb][kc1 * 4 + 0][row1] = stA1.x; As[nb][kc1 * 4 + 1][row1] = stA1.y;
            As[nb][kc1 * 4 + 2][row1] = stA1.z; As[nb][kc1 * 4 + 3][row1] = stA1.w;
            Bs[nb][kc0 * 4 + 0][row0] = stB0.x; Bs[nb][kc0 * 4 + 1][row0] = stB0.y;
            Bs[nb][kc0 * 4 + 2][row0] = stB0.z; Bs[nb][kc0 * 4 + 3][row0] = stB0.w;
            Bs[nb][kc1 * 4 + 0][row1] = stB1.x; Bs[nb][kc1 * 4 + 1][row1] = stB1.y;
            Bs[nb][kc1 * 4 + 2][row1] = stB1.z; Bs[nb][kc1 * 4 + 3][row1] = stB1.w;
        }
        __syncthreads();
    }

    float bias[8];
#pragma unroll
    for (int c = 0; c < 8; ++c) {
        int n = n0 + tx * 8 + c;
        bias[c] = bi1[n] + b11[n];
    }
    float* X1t = g_X1 + (size_t)tstep * BATCH * H;
#pragma unroll
    for (int r2 = 0; r2 < 4; ++r2) {
        float lo[8], hi[8];
#pragma unroll
        for (int c = 0; c < 8; ++c) unpack2(acc[r2][c], lo[c], hi[c]);
        int bA = ty * 8 + 2 * r2;
        int bB = bA + 1;
        int n = n0 + tx * 8;
        float4* pA = (float4*)(X1t + (size_t)bA * H + n);
        float4* pB = (float4*)(X1t + (size_t)bB * H + n);
        pA[0] = make_float4(lo[0] + bias[0], lo[1] + bias[1], lo[2] + bias[2], lo[3] + bias[3]);
        pA[1] = make_float4(lo[4] + bias[4], lo[5] + bias[5], lo[6] + bias[6], lo[7] + bias[7]);
        pB[0] = make_float4(hi[0] + bias[0], hi[1] + bias[1], hi[2] + bias[2], hi[3] + bias[3]);
        pB[1] = make_float4(hi[4] + bias[4], hi[5] + bias[5], hi[6] + bias[6], hi[7] + bias[7]);
    }
}

// ---------------------------------------------------------------------------
__device__ __forceinline__ void acc4(const float* __restrict__ W,
                                     int4 j, int col, float4& h) {
    float4 v0 = *(const float4*)(W + j.x * H + col);
    float4 v1 = *(const float4*)(W + j.y * H + col);
    float4 v2 = *(const float4*)(W + j.z * H + col);
    float4 v3 = *(const float4*)(W + j.w * H + col);
    h.x += (v0.x + v1.x) + (v2.x + v3.x);
    h.y += (v0.y + v1.y) + (v2.y + v3.y);
    h.z += (v0.z + v1.z) + (v2.z + v3.z);
    h.w += (v0.w + v1.w) + (v2.w + v3.w);
}

// ---------------------------------------------------------------------------
// Persistent RNN: one CTA per sample, 544 threads.
//   warps 0-15 (512 thr): workers — R10's segmented-list pipeline, with
//     phases (a/b/c) on named barrier 1 (512 threads) and the step boundary
//     (d) on __syncthreads (all 544).
//   warp 16: output-only — after each (d) it sums the (double-buffered)
//     pout partials and runs memo/softmax/acc with a full step of slack,
//     so the softmax chain never gates the workers' barriers.
// Phase A gathers W11 only; phase B gathers W12 + W22 (both consumed by u2).
// ---------------------------------------------------------------------------
__global__ __launch_bounds__(544, 1) void rnn_kernel(
    const float* __restrict__ mem1_0, const float* __restrict__ mem2_0,
    const float* __restrict__ memo_0,
    const float* __restrict__ b12v, const float* __restrict__ b22v,
    const float* __restrict__ Wo, const float* __restrict__ bov,
    const float* __restrict__ tau_adp1, const float* __restrict__ tau_adp2,
    const float* __restrict__ tau_m1, const float* __restrict__ tau_m2,
    const float* __restrict__ tau_mo,
    float* __restrict__ out) {
    __shared__ __align__(16) int list1[2][H];
    __shared__ __align__(16) int list2[2][H];
    __shared__ int cntp1[2][8], cntp2[2][8];   // padded per-segment counts
    __shared__ float part11[8][H];
    __shared__ float part22[8][H];
    __shared__ float part12[8][H];
    __shared__ float pout[2][8][32];           // double-buffered by phase
    __shared__ float sWoT[(H + 1) * DOUT];

    int b = blockIdx.x;
    int tid = threadIdx.x;
    bool is_worker = tid < 512;
    int lane = tid & 31, warp = tid >> 5;
    int rep = (tid >> 6) & 7;
    int col = (tid & 63) << 2;

    for (int idx = tid; idx < H * DOUT; idx += 544) {
        int j = idx / DOUT, k = idx - j * DOUT;
        sWoT[idx] = Wo[k * H + j];
    }
    if (tid < DOUT) sWoT[H * DOUT + tid] = 0.f;
    if (tid < 8) {
        cntp1[0][tid] = 0; cntp1[1][tid] = 0;
        cntp2[0][tid] = 0; cntp2[1][tid] = 0;
    }

    // worker (owner) state
    float mem1 = 0.f, sp1 = 0.f, ab1 = 0.01f, al1 = 0.f, ro1 = 0.f;
    float mem2 = 0.f, sp2 = 0.f, ab2 = 0.01f, al2 = 0.f, ro2 = 0.f;
    float hb2 = 0.f;
    if (is_worker && tid < 256) {
        mem1 = mem1_0[b * H + tid];
        al1 = expf(-1.f / tau_m1[tid]);
        ro1 = expf(-1.f / tau_adp1[tid]);
        mem2 = mem2_0[b * H + tid];
        al2 = expf(-1.f / tau_m2[tid]);
        ro2 = expf(-1.f / tau_adp2[tid]);
        hb2 = b12v[tid] + b22v[tid];
    }
    // output-warp state (warp 16)
    float memo = 0.f, alo = 0.f, omo = 0.f, bok = 0.f, accv = 0.f;
    if (!is_worker && lane < DOUT) {
        memo = memo_0[b * DOUT + lane];
        alo = expf(-1.f / tau_mo[lane]); omo = 1.f - alo;
        bok = bov[lane];
    }
    __syncthreads();

    if (is_worker) {
        int p = 0;
        float x1cur = (tid < 256) ? g_X1[(size_t)b * H + tid] : 0.f;

        for (int t = 0; t < TT; ++t) {
            int pn = p ^ 1;

            float x1nxt = 0.f;
            if (tid < 256 && t + 1 < TT)
                x1nxt = g_X1[((size_t)(t + 1) * BATCH + b) * H + tid];

            // ---- phase A: W11 gather (old sp1) ----
            {
                float4 a11 = make_float4(0.f, 0.f, 0.f, 0.f);
#pragma unroll
                for (int seg = 0; seg < 8; ++seg) {
                    int ch = (rep + seg) & 7;
                    int c1 = cntp1[p][seg];
                    const int4* s1 = (const int4*)&list1[p][seg << 5];
                    if ((ch << 2) < c1) acc4(g_W11T, s1[ch], col, a11);
                }
                *(float4*)&part11[rep][col] = a11;
            }
            bar_workers();   // (a)

            // ---- layer 1 update + segmented list write (owners) ----
            if (tid < 256) {
                float h1 = x1cur;
#pragma unroll
                for (int r = 0; r < 8; ++r) h1 += part11[r][tid];
                ab1 = ro1 * ab1 + (1.f - ro1) * sp1;
                float B = 0.01f + 1.8f * ab1;
                mem1 = mem1 * al1 + (1.f - al1) * h1 - B * sp1;
                float sp1n = (mem1 - B) > 0.f ? 1.f : 0.f;
                unsigned bal = __ballot_sync(0xffffffffu, sp1n != 0.f);
                int cw = __popc(bal);
                int cwp = (cw + 3) & ~3;
                unsigned ltm = (1u << lane) - 1u;
                if (sp1n != 0.f) {
                    list1[pn][(warp << 5) + __popc(bal & ltm)] = tid;
                } else {
                    int np = __popc(~bal & ltm);
                    if (np < cwp - cw) list1[pn][(warp << 5) + cw + np] = 256;
                }
                if (lane == 0) cntp1[pn][warp] = cwp;
                sp1 = sp1n;
            }
            bar_workers();   // (b)

            // ---- phase B: W12 gather (new sp1) + W22 gather (old sp2) ----
            {
                float4 a12 = make_float4(0.f, 0.f, 0.f, 0.f);
                float4 a22 = make_float4(0.f, 0.f, 0.f, 0.f);
#pragma unroll
                for (int seg = 0; seg < 8; ++seg) {
                    int ch = (rep + seg) & 7;
                    int c4 = ch << 2;
                    int c1 = cntp1[pn][seg];
                    int c2 = cntp2[p][seg];
                    const int4* s1 = (const int4*)&list1[pn][seg << 5];
                    const int4* s2 = (const int4*)&list2[p][seg << 5];
                    if (c4 < c1) acc4(g_W12T, s1[ch], col, a12);
                    if (c4 < c2) acc4(g_W22T, s2[ch], col, a22);
                }
                *(float4*)&part12[rep][col] = a12;
                *(float4*)&part22[rep][col] = a22;
            }
            bar_workers();   // (c)

            // ---- layer 2 update + list write + pout partial (owners) ----
            if (tid < 256) {
                float h2 = hb2;
#pragma unroll
                for (int r = 0; r < 8; ++r) h2 += part12[r][tid];
#pragma unroll
                for (int r = 0; r < 8; ++r) h2 += part22[r][tid];
                ab2 = ro2 * ab2 + (1.f - ro2) * sp2;
                float B = 0.01f + 1.8f * ab2;
                mem2 = mem2 * al2 + (1.f - al2) * h2 - B * sp2;
                float sp2n = (mem2 - B) > 0.f ? 1.f : 0.f;
                unsigned bal = __ballot_sync(0xffffffffu, sp2n != 0.f);
                int cw = __popc(bal);
                int cwp = (cw + 3) & ~3;
                unsigned ltm = (1u << lane) - 1u;
                if (sp2n != 0.f) {
                    list2[pn][(warp << 5) + __popc(bal & ltm)] = tid;
                } else {
                    int np = __popc(~bal & ltm);
                    if (np < cwp - cw) list2[pn][(warp << 5) + cw + np] = 256;
                }
                if (lane == 0) cntp2[pn][warp] = cwp;
                sp2 = sp2n;

                // output partial for this warp's 32 neurons
                int kk = lane < DOUT ? lane : 0;
                float o = 0.f;
                unsigned mm = bal;
                int jb = warp << 5;
                while (mm) {
                    int l = __ffs(mm) - 1;
                    mm &= mm - 1;
                    o += sWoT[(jb + l) * DOUT + kk];
                }
                pout[pn][warp][lane] = o;
            }
            __syncthreads();   // (d) — all 544 threads

            p = pn;
            x1cur = x1nxt;
        }
    } else {
        // ---- warp 16: output/softmax, one full step of slack ----
        int p = 0;
        for (int t = 0; t < TT; ++t) {
            int pn = p ^ 1;
            __syncthreads();   // (d) of step t
            float o = bok;
#pragma unroll
            for (int g = 0; g < 8; ++g) o += pout[pn][g][lane];
            memo = memo * alo + omo * o;
            float e = lane < DOUT ? __expf(memo) : 0.f;
            float ss = e;
#pragma unroll
            for (int sh = 16; sh > 0; sh >>= 1)
                ss += __shfl_xor_sync(0xffffffffu, ss, sh);
            if (t > 10) accv += e / ss;
            p = pn;
        }
        if (lane < DOUT) out[b * DOUT + lane] = accv;
    }
}

// ---------------------------------------------------------------------------
// Serial single-stream launch (overlap permanently abandoned: R6/R8/R11).
// ---------------------------------------------------------------------------
extern "C" void kernel_launch(void* const* d_in, const int* in_sizes, int n_in,
                              void* d_out, int out_size) {
    const float* x        = (const float*)d_in[0];
    const float* mem1_0   = (const float*)d_in[1];
    const float* mem2_0   = (const float*)d_in[2];
    const float* memo_0   = (const float*)d_in[3];
    const float* Wi1      = (const float*)d_in[4];
    const float* bi1      = (const float*)d_in[5];
    const float* W11      = (const float*)d_in[6];
    const float* b11      = (const float*)d_in[7];
    const float* W12      = (const float*)d_in[8];
    const float* b12      = (const float*)d_in[9];
    const float* W22      = (const float*)d_in[10];
    const float* b22      = (const float*)d_in[11];
    const float* Wo       = (const float*)d_in[12];
    const float* bo       = (const float*)d_in[13];
    const float* tau_adp1 = (const float*)d_in[14];
    const float* tau_adp2 = (const float*)d_in[15];
    const float* tau_m1   = (const float*)d_in[16];
    const float* tau_m2   = (const float*)d_in[17];
    const float* tau_mo   = (const float*)d_in[18];
    float* out = (float*)d_out;

    transpose_weights_kernel<<<(3 * H * H + 3 * H + 255) / 256, 256>>>(W11, W12, W22);
    dim3 g(H / GBN, TT);   // (2, 250): block y == timestep
    gemm_x1_kernel<<<g, 256>>>(x, Wi1, bi1, b11);
    rnn_kernel<<<BATCH, 544>>>(mem1_0, mem2_0, memo_0, b12, b22, Wo, bo,
                               tau_adp1, tau_adp2, tau_m1, tau_m2, tau_mo, out);
}

// round 14
// speedup vs baseline: 1.3386x; 1.0743x over previous
#include <cuda_runtime.h>
#include <math.h>

#define H 256
#define DIN 700
#define DOUT 20
#define BATCH 128
#define TT 250

// Scratch (device globals). g_X1 is T-MAJOR: X1[t][b][i].
// Weight tables have an extra all-zero row (index 256) for padded gathers.
__device__ float g_X1[(size_t)TT * BATCH * H];
__device__ float g_W11T[(H + 1) * H];
__device__ float g_W12T[(H + 1) * H];
__device__ float g_W22T[(H + 1) * H];

// ---------------------------------------------------------------------------
__device__ __forceinline__ void ffma2(unsigned long long& acc,
                                      unsigned long long a,
                                      unsigned long long b) {
    asm("fma.rn.f32x2 %0, %1, %2, %0;" : "+l"(acc) : "l"(a), "l"(b));
}
__device__ __forceinline__ unsigned long long pack2(float lo, float hi) {
    unsigned long long r;
    asm("mov.b64 %0, {%1, %2};" : "=l"(r) : "f"(lo), "f"(hi));
    return r;
}
__device__ __forceinline__ void unpack2(unsigned long long v, float& lo, float& hi) {
    asm("mov.b64 {%0, %1}, %2;" : "=f"(lo), "=f"(hi) : "l"(v));
}
// Named barrier over the 512 worker threads (warps 0-15).
__device__ __forceinline__ void bar_workers() {
    asm volatile("bar.sync 1, 512;" ::: "memory");
}
// Step-boundary producer/consumer barrier (id 2, 544 threads total):
// workers arrive (non-blocking), output warp syncs (blocks until all arrive).
__device__ __forceinline__ void bar_step_arrive() {
    asm volatile("bar.arrive 2, 544;" ::: "memory");
}
__device__ __forceinline__ void bar_step_sync() {
    asm volatile("bar.sync 2, 544;" ::: "memory");
}

// ---------------------------------------------------------------------------
__global__ void transpose_weights_kernel(const float* __restrict__ W11,
                                         const float* __restrict__ W12,
                                         const float* __restrict__ W22) {
    int idx = blockIdx.x * blockDim.x + threadIdx.x;
    if (idx < 3 * H * H) {
        int m = idx >> 16;
        int r = (idx >> 8) & 255;
        int c = idx & 255;
        if (m == 0)      g_W11T[c * H + r] = W11[r * H + c];
        else if (m == 1) g_W12T[c * H + r] = W12[r * H + c];
        else             g_W22T[c * H + r] = W22[r * H + c];
    } else {
        int w = idx - 3 * H * H;
        if (w < 3 * H) {
            int m = w >> 8, c = w & 255;
            if (m == 0)      g_W11T[256 * H + c] = 0.f;
            else if (m == 1) g_W12T[256 * H + c] = 0.f;
            else             g_W22T[256 * H + c] = 0.f;
        }
    }
}

// ---------------------------------------------------------------------------
// X1[t][b][:] = x[b][t][:] @ Wi1.T + (bi1 + b11). Block y == timestep.
// (R10's proven serial GEMM, unchanged.)
// ---------------------------------------------------------------------------
#define GBM 128
#define GBN 128
#define GBK 16
#define GPAD 4
#define GNT ((DIN + GBK - 1) / GBK)

__global__ __launch_bounds__(256, 2) void gemm_x1_kernel(
    const float* __restrict__ x, const float* __restrict__ Wi1,
    const float* __restrict__ bi1, const float* __restrict__ b11) {
    __shared__ float As[2][GBK][GBM + GPAD];
    __shared__ float Bs[2][GBK][GBN + GPAD];

    int tid = threadIdx.x;
    int tstep = blockIdx.y;
    int n0 = blockIdx.x * GBN;
    int tx = tid & 15, ty = tid >> 4;

    int row0 = tid >> 2,          kc0 = tid & 3;
    int row1 = (256 + tid) >> 2,  kc1 = tid & 3;

    const float* xr0 = x + ((size_t)row0 * TT + tstep) * DIN;
    const float* xr1 = x + ((size_t)row1 * TT + tstep) * DIN;

    unsigned long long acc[4][8];
#pragma unroll
    for (int r = 0; r < 4; ++r)
#pragma unroll
        for (int c = 0; c < 8; ++c) acc[r][c] = 0ull;

    float4 stA0, stA1, stB0, stB1;

    {
        int kA0 = kc0 * 4, kA1 = kc1 * 4;
        stA0 = *(const float4*)(xr0 + kA0);
        stA1 = *(const float4*)(xr1 + kA1);
        stB0 = *(const float4*)(Wi1 + (size_t)(n0 + row0) * DIN + kA0);
        stB1 = *(const float4*)(Wi1 + (size_t)(n0 + row1) * DIN + kA1);
        As[0][kc0 * 4 + 0][row0] = stA0.x; As[0][kc0 * 4 + 1][row0] = stA0.y;
        As[0][kc0 * 4 + 2][row0] = stA0.z; As[0][kc0 * 4 + 3][row0] = stA0.w;
        As[0][kc1 * 4 + 0][row1] = stA1.x; As[0][kc1 * 4 + 1][row1] = stA1.y;
        As[0][kc1 * 4 + 2][row1] = stA1.z; As[0][kc1 * 4 + 3][row1] = stA1.w;
        Bs[0][kc0 * 4 + 0][row0] = stB0.x; Bs[0][kc0 * 4 + 1][row0] = stB0.y;
        Bs[0][kc0 * 4 + 2][row0] = stB0.z; Bs[0][kc0 * 4 + 3][row0] = stB0.w;
        Bs[0][kc1 * 4 + 0][row1] = stB1.x; Bs[0][kc1 * 4 + 1][row1] = stB1.y;
        Bs[0][kc1 * 4 + 2][row1] = stB1.z; Bs[0][kc1 * 4 + 3][row1] = stB1.w;
    }
    __syncthreads();

    for (int t = 0; t < GNT; ++t) {
        int buf = t & 1;

        if (t + 1 < GNT) {
            int kb = (t + 1) * GBK;
            int kA0 = kb + kc0 * 4, kA1 = kb + kc1 * 4;
            stA0 = (kA0 < DIN) ? *(const float4*)(xr0 + kA0) : make_float4(0.f,0.f,0.f,0.f);
            stA1 = (kA1 < DIN) ? *(const float4*)(xr1 + kA1) : make_float4(0.f,0.f,0.f,0.f);
            stB0 = (kA0 < DIN) ? *(const float4*)(Wi1 + (size_t)(n0 + row0) * DIN + kA0)
                               : make_float4(0.f, 0.f, 0.f, 0.f);
            stB1 = (kA1 < DIN) ? *(const float4*)(Wi1 + (size_t)(n0 + row1) * DIN + kA1)
                               : make_float4(0.f, 0.f, 0.f, 0.f);
        }

#pragma unroll
        for (int kk = 0; kk < GBK; ++kk) {
            ulonglong2 aA = *(const ulonglong2*)&As[buf][kk][ty * 8];
            ulonglong2 aB = *(const ulonglong2*)&As[buf][kk][ty * 8 + 4];
            float4 b0 = *(const float4*)&Bs[buf][kk][tx * 8];
            float4 b1 = *(const float4*)&Bs[buf][kk][tx * 8 + 4];
            float barr[8] = {b0.x, b0.y, b0.z, b0.w, b1.x, b1.y, b1.z, b1.w};
#pragma unroll
            for (int c = 0; c < 8; ++c) {
                unsigned long long bb = pack2(barr[c], barr[c]);
                ffma2(acc[0][c], aA.x, bb);
                ffma2(acc[1][c], aA.y, bb);
                ffma2(acc[2][c], aB.x, bb);
                ffma2(acc[3][c], aB.y, bb);
            }
        }

        if (t + 1 < GNT) {
            int nb = buf ^ 1;
            As[nb][kc0 * 4 + 0][row0] = stA0.x; As[nb][kc0 * 4 + 1][row0] = stA0.y;
            As[nb][kc0 * 4 + 2][row0] = stA0.z; As[nb][kc0 * 4 + 3][row0] = stA0.w;
            As[nb][kc1 * 4 + 0][row1] = stA1.x; As[nb][kc1 * 4 + 1][row1] = stA1.y;
            As[nb][kc1 * 4 + 2][row1] = stA1.z; As[nb][kc1 * 4 + 3][row1] = stA1.w;
            Bs[nb][kc0 * 4 + 0][row0] = stB0.x; Bs[nb][kc0 * 4 + 1][row0] = stB0.y;
            Bs[nb][kc0 * 4 + 2][row0] = stB0.z; Bs[nb][kc0 * 4 + 3][row0] = stB0.w;
            Bs[nb][kc1 * 4 + 0][row1] = stB1.x; Bs[nb][kc1 * 4 + 1][row1] = stB1.y;
            Bs[nb][kc1 * 4 + 2][row1] = stB1.z; Bs[nb][kc1 * 4 + 3][row1] = stB1.w;
        }
        __syncthreads();
    }

    float bias[8];
#pragma unroll
    for (int c = 0; c < 8; ++c) {
        int n = n0 + tx * 8 + c;
        bias[c] = bi1[n] + b11[n];
    }
    float* X1t = g_X1 + (size_t)tstep * BATCH * H;
#pragma unroll
    for (int r2 = 0; r2 < 4; ++r2) {
        float lo[8], hi[8];
#pragma unroll
        for (int c = 0; c < 8; ++c) unpack2(acc[r2][c], lo[c], hi[c]);
        int bA = ty * 8 + 2 * r2;
        int bB = bA + 1;
        int n = n0 + tx * 8;
        float4* pA = (float4*)(X1t + (size_t)bA * H + n);
        float4* pB = (float4*)(X1t + (size_t)bB * H + n);
        pA[0] = make_float4(lo[0] + bias[0], lo[1] + bias[1], lo[2] + bias[2], lo[3] + bias[3]);
        pA[1] = make_float4(lo[4] + bias[4], lo[5] + bias[5], lo[6] + bias[6], lo[7] + bias[7]);
        pB[0] = make_float4(hi[0] + bias[0], hi[1] + bias[1], hi[2] + bias[2], hi[3] + bias[3]);
        pB[1] = make_float4(hi[4] + bias[4], hi[5] + bias[5], hi[6] + bias[6], hi[7] + bias[7]);
    }
}

// ---------------------------------------------------------------------------
__device__ __forceinline__ void acc4(const float* __restrict__ W,
                                     int4 j, int col, float4& h) {
    float4 v0 = *(const float4*)(W + j.x * H + col);
    float4 v1 = *(const float4*)(W + j.y * H + col);
    float4 v2 = *(const float4*)(W + j.z * H + col);
    float4 v3 = *(const float4*)(W + j.w * H + col);
    h.x += (v0.x + v1.x) + (v2.x + v3.x);
    h.y += (v0.y + v1.y) + (v2.y + v3.y);
    h.z += (v0.z + v1.z) + (v2.z + v3.z);
    h.w += (v0.w + v1.w) + (v2.w + v3.w);
}

// ---------------------------------------------------------------------------
// Persistent RNN: one CTA per sample, 544 threads.
//   warps 0-15 (512 thr): workers — segmented-list pipeline (bar 1);
//     step boundary is a NON-BLOCKING bar.arrive (id 2).
//   warp 16: output-only — bar.sync (id 2) each step, then sums the
//     double-buffered pout partials + softmax with a full step of slack.
// X1 is prefetched TWO steps ahead so its L2/DRAM latency is fully hidden.
// Segment counts are read as int4 pairs (2 LDS instead of 8 per table).
// ---------------------------------------------------------------------------
__global__ __launch_bounds__(544, 1) void rnn_kernel(
    const float* __restrict__ mem1_0, const float* __restrict__ mem2_0,
    const float* __restrict__ memo_0,
    const float* __restrict__ b12v, const float* __restrict__ b22v,
    const float* __restrict__ Wo, const float* __restrict__ bov,
    const float* __restrict__ tau_adp1, const float* __restrict__ tau_adp2,
    const float* __restrict__ tau_m1, const float* __restrict__ tau_m2,
    const float* __restrict__ tau_mo,
    float* __restrict__ out) {
    __shared__ __align__(16) int list1[2][H];
    __shared__ __align__(16) int list2[2][H];
    __shared__ __align__(16) int cntp1[2][8];
    __shared__ __align__(16) int cntp2[2][8];
    __shared__ float part11[8][H];
    __shared__ float part22[8][H];
    __shared__ float part12[8][H];
    __shared__ float pout[2][8][32];           // double-buffered by phase
    __shared__ float sWoT[(H + 1) * DOUT];

    int b = blockIdx.x;
    int tid = threadIdx.x;
    bool is_worker = tid < 512;
    int lane = tid & 31, warp = tid >> 5;
    int rep = (tid >> 6) & 7;
    int col = (tid & 63) << 2;

    for (int idx = tid; idx < H * DOUT; idx += 544) {
        int j = idx / DOUT, k = idx - j * DOUT;
        sWoT[idx] = Wo[k * H + j];
    }
    if (tid < DOUT) sWoT[H * DOUT + tid] = 0.f;
    if (tid < 8) {
        cntp1[0][tid] = 0; cntp1[1][tid] = 0;
        cntp2[0][tid] = 0; cntp2[1][tid] = 0;
    }

    // worker (owner) state
    float mem1 = 0.f, sp1 = 0.f, ab1 = 0.01f, al1 = 0.f, ro1 = 0.f;
    float mem2 = 0.f, sp2 = 0.f, ab2 = 0.01f, al2 = 0.f, ro2 = 0.f;
    float hb2 = 0.f;
    if (is_worker && tid < 256) {
        mem1 = mem1_0[b * H + tid];
        al1 = expf(-1.f / tau_m1[tid]);
        ro1 = expf(-1.f / tau_adp1[tid]);
        mem2 = mem2_0[b * H + tid];
        al2 = expf(-1.f / tau_m2[tid]);
        ro2 = expf(-1.f / tau_adp2[tid]);
        hb2 = b12v[tid] + b22v[tid];
    }
    // output-warp state (warp 16)
    float memo = 0.f, alo = 0.f, omo = 0.f, bok = 0.f, accv = 0.f;
    if (!is_worker && lane < DOUT) {
        memo = memo_0[b * DOUT + lane];
        alo = expf(-1.f / tau_mo[lane]); omo = 1.f - alo;
        bok = bov[lane];
    }
    __syncthreads();

    if (is_worker) {
        int p = 0;
        // X1 double prefetch: two loads in flight at all times.
        float x1cur = 0.f, x1n1 = 0.f;
        if (tid < 256) {
            x1cur = g_X1[(size_t)b * H + tid];
            x1n1  = g_X1[((size_t)BATCH + b) * H + tid];
        }

        for (int t = 0; t < TT; ++t) {
            int pn = p ^ 1;

            float x1n2 = 0.f;
            if (tid < 256 && t + 2 < TT)
                x1n2 = g_X1[((size_t)(t + 2) * BATCH + b) * H + tid];

            // ---- phase A: W11 gather (old sp1) ----
            {
                int cc[8];
                *(int4*)&cc[0] = *(const int4*)&cntp1[p][0];
                *(int4*)&cc[4] = *(const int4*)&cntp1[p][4];
                float4 a11 = make_float4(0.f, 0.f, 0.f, 0.f);
#pragma unroll
                for (int seg = 0; seg < 8; ++seg) {
                    int ch = (rep + seg) & 7;
                    const int4* s1 = (const int4*)&list1[p][seg << 5];
                    if ((ch << 2) < cc[seg]) acc4(g_W11T, s1[ch], col, a11);
                }
                *(float4*)&part11[rep][col] = a11;
            }
            bar_workers();   // (a)

            // ---- layer 1 update + segmented list write (owners) ----
            if (tid < 256) {
                float h1 = x1cur;
#pragma unroll
                for (int r = 0; r < 8; ++r) h1 += part11[r][tid];
                ab1 = ro1 * ab1 + (1.f - ro1) * sp1;
                float B = 0.01f + 1.8f * ab1;
                mem1 = mem1 * al1 + (1.f - al1) * h1 - B * sp1;
                float sp1n = (mem1 - B) > 0.f ? 1.f : 0.f;
                unsigned bal = __ballot_sync(0xffffffffu, sp1n != 0.f);
                int cw = __popc(bal);
                int cwp = (cw + 3) & ~3;
                unsigned ltm = (1u << lane) - 1u;
                if (sp1n != 0.f) {
                    list1[pn][(warp << 5) + __popc(bal & ltm)] = tid;
                } else {
                    int np = __popc(~bal & ltm);
                    if (np < cwp - cw) list1[pn][(warp << 5) + cw + np] = 256;
                }
                if (lane == 0) cntp1[pn][warp] = cwp;
                sp1 = sp1n;
            }
            bar_workers();   // (b)

            // ---- phase B: W12 gather (new sp1) + W22 gather (old sp2) ----
            {
                int c1[8], c2[8];
                *(int4*)&c1[0] = *(const int4*)&cntp1[pn][0];
                *(int4*)&c1[4] = *(const int4*)&cntp1[pn][4];
                *(int4*)&c2[0] = *(const int4*)&cntp2[p][0];
                *(int4*)&c2[4] = *(const int4*)&cntp2[p][4];
                float4 a12 = make_float4(0.f, 0.f, 0.f, 0.f);
                float4 a22 = make_float4(0.f, 0.f, 0.f, 0.f);
#pragma unroll
                for (int seg = 0; seg < 8; ++seg) {
                    int ch = (rep + seg) & 7;
                    int c4 = ch << 2;
                    const int4* s1 = (const int4*)&list1[pn][seg << 5];
                    const int4* s2 = (const int4*)&list2[p][seg << 5];
                    if (c4 < c1[seg]) acc4(g_W12T, s1[ch], col, a12);
                    if (c4 < c2[seg]) acc4(g_W22T, s2[ch], col, a22);
                }
                *(float4*)&part12[rep][col] = a12;
                *(float4*)&part22[rep][col] = a22;
            }
            bar_workers();   // (c)

            // ---- layer 2 update + list write + pout partial (owners) ----
            if (tid < 256) {
                float h2 = hb2;
#pragma unroll
                for (int r = 0; r < 8; ++r) h2 += part12[r][tid];
#pragma unroll
                for (int r = 0; r < 8; ++r) h2 += part22[r][tid];
                ab2 = ro2 * ab2 + (1.f - ro2) * sp2;
                float B = 0.01f + 1.8f * ab2;
                mem2 = mem2 * al2 + (1.f - al2) * h2 - B * sp2;
                float sp2n = (mem2 - B) > 0.f ? 1.f : 0.f;
                unsigned bal = __ballot_sync(0xffffffffu, sp2n != 0.f);
                int cw = __popc(bal);
                int cwp = (cw + 3) & ~3;
                unsigned ltm = (1u << lane) - 1u;
                if (sp2n != 0.f) {
                    list2[pn][(warp << 5) + __popc(bal & ltm)] = tid;
                } else {
                    int np = __popc(~bal & ltm);
                    if (np < cwp - cw) list2[pn][(warp << 5) + cw + np] = 256;
                }
                if (lane == 0) cntp2[pn][warp] = cwp;
                sp2 = sp2n;

                // output partial for this warp's 32 neurons
                int kk = lane < DOUT ? lane : 0;
                float o = 0.f;
                unsigned mm = bal;
                int jb = warp << 5;
                while (mm) {
                    int l = __ffs(mm) - 1;
                    mm &= mm - 1;
                    o += sWoT[(jb + l) * DOUT + kk];
                }
                pout[pn][warp][lane] = o;
            }
            bar_step_arrive();   // (d) non-blocking for workers

            p = pn;
            x1cur = x1n1;
            x1n1 = x1n2;
        }
    } else {
        // ---- warp 16: output/softmax, one full step of slack ----
        int p = 0;
        for (int t = 0; t < TT; ++t) {
            int pn = p ^ 1;
            bar_step_sync();   // (d) of step t — blocks until workers arrive
            float o = bok;
#pragma unroll
            for (int g = 0; g < 8; ++g) o += pout[pn][g][lane];
            memo = memo * alo + omo * o;
            if (t > 10) {
                float e = lane < DOUT ? __expf(memo) : 0.f;
                float ss = e;
#pragma unroll
                for (int sh = 16; sh > 0; sh >>= 1)
                    ss += __shfl_xor_sync(0xffffffffu, ss, sh);
                accv += e / ss;
            }
            p = pn;
        }
        if (lane < DOUT) out[b * DOUT + lane] = accv;
    }
}

// ---------------------------------------------------------------------------
// Serial single-stream launch (overlap permanently abandoned: R6/R8/R11).
// ---------------------------------------------------------------------------
extern "C" void kernel_launch(void* const* d_in, const int* in_sizes, int n_in,
                              void* d_out, int out_size) {
    const float* x        = (const float*)d_in[0];
    const float* mem1_0   = (const float*)d_in[1];
    const float* mem2_0   = (const float*)d_in[2];
    const float* memo_0   = (const float*)d_in[3];
    const float* Wi1      = (const float*)d_in[4];
    const float* bi1      = (const float*)d_in[5];
    const float* W11      = (const float*)d_in[6];
    const float* b11      = (const float*)d_in[7];
    const float* W12      = (const float*)d_in[8];
    const float* b12      = (const float*)d_in[9];
    const float* W22      = (const float*)d_in[10];
    const float* b22      = (const float*)d_in[11];
    const float* Wo       = (const float*)d_in[12];
    const float* bo       = (const float*)d_in[13];
    const float* tau_adp1 = (const float*)d_in[14];
    const float* tau_adp2 = (const float*)d_in[15];
    const float* tau_m1   = (const float*)d_in[16];
    const float* tau_m2   = (const float*)d_in[17];
    const float* tau_mo   = (const float*)d_in[18];
    float* out = (float*)d_out;

    transpose_weights_kernel<<<(3 * H * H + 3 * H + 255) / 256, 256>>>(W11, W12, W22);
    dim3 g(H / GBN, TT);   // (2, 250): block y == timestep
    gemm_x1_kernel<<<g, 256>>>(x, Wi1, bi1, b11);
    rnn_kernel<<<BATCH, 544>>>(mem1_0, mem2_0, memo_0, b12, b22, Wo, bo,
                               tau_adp1, tau_adp2, tau_m1, tau_m2, tau_mo, out);
}